// round 15
// baseline (speedup 1.0000x reference)
#include <cuda_runtime.h>
#include <cuda_fp16.h>
#include <math.h>
#include <cstdint>

// Problem constants
#define B_    128
#define C_    2048
#define S_    196          // H*W = 14*14
#define HID_  1024
#define T_    20
#define M_    (B_*S_)      // 25088

// ---------------------------------------------------------------------------
// Scratch (allocation-free rule: __device__ globals)
// Pure fp16 operands, fp32 accumulation inside the GEMMs.
// ---------------------------------------------------------------------------
__device__ __half g_a1 [(size_t)M_*C_];      // v_i transposed fp16  [M,2048]
__device__ __half g_vi [(size_t)M_*HID_];    // vi = tanh(l1) fp16   [M,1024]
__device__ __half g_z  [(size_t)M_*2*HID_];  // z0|z1 fp16 [M,2048]
__device__ __half g_l1w[(size_t)HID_*C_];    // l1_w fp16
__device__ __half g_wc [(size_t)2*HID_*HID_];// w0|w1 fp16
__device__ float g_u0 [B_*HID_];
__device__ float g_u1 [B_*HID_];
__device__ float g_vqt[B_*HID_];

// ---------------------------------------------------------------------------
// Portable PTX helpers: ldmatrix / mma.sync / cp.async
// ---------------------------------------------------------------------------
__device__ __forceinline__ uint32_t smem_to_u32(const void* p) {
    uint32_t a;
    asm("{ .reg .u64 tmp; cvta.to.shared.u64 tmp, %1; cvt.u32.u64 %0, tmp; }"
        : "=r"(a) : "l"(p));
    return a;
}
__device__ __forceinline__ void ldmatrix_x4(uint32_t* r, uint32_t addr) {
    asm volatile("ldmatrix.sync.aligned.m8n8.x4.shared.b16 {%0,%1,%2,%3}, [%4];"
        : "=r"(r[0]), "=r"(r[1]), "=r"(r[2]), "=r"(r[3]) : "r"(addr));
}
__device__ __forceinline__ void mma_16816(float* d, const uint32_t* a, const uint32_t* b) {
    asm volatile(
        "mma.sync.aligned.m16n8k16.row.col.f32.f16.f16.f32 "
        "{%0,%1,%2,%3}, {%4,%5,%6,%7}, {%8,%9}, {%0,%1,%2,%3};"
        : "+f"(d[0]), "+f"(d[1]), "+f"(d[2]), "+f"(d[3])
        : "r"(a[0]), "r"(a[1]), "r"(a[2]), "r"(a[3]), "r"(b[0]), "r"(b[1]));
}
__device__ __forceinline__ void ldgsts16(uint32_t dst, const void* src) {
    asm volatile("cp.async.cg.shared.global [%0], [%1], 16;" :: "r"(dst), "l"(src) : "memory");
}
#define CP_COMMIT() asm volatile("cp.async.commit_group;" ::: "memory")
#define CP_WAIT1()  asm volatile("cp.async.wait_group 1;" ::: "memory")

// ---------------------------------------------------------------------------
// fp16 HMMA GEMM: C[M,N] = A[M,K] @ B[N,K]^T, fp32 accum.
// CTA tile 128x128, K-chunk 64, 4 warps (2x2 grid, 64x64 warp tiles),
// 128 threads, 3-stage cp.async pipeline (prefetch-first), 2 CTAs/SM.
// Per k16 slice per warp: 8 ldmatrix feed 32 independent MMAs (0.25 LDSM/MMA),
// 128 MMAs per chunk per warp -> barrier overhead halved vs 64x32 warps.
// SMEM per stage: A[128][144B] (128B data + 16B pad) then B likewise.
// 144B = 16*9 (odd multiple of 16) -> conflict-free ldmatrix + cp.async.
// EPI=0: fp16 out (ld=ldo).  EPI=1: tanh(C+bias) -> fp16 (ld=HID_).
// ---------------------------------------------------------------------------
#define ROW_T    144
#define BOFF     (128*ROW_T)          // 18432
#define STAGE_B  (2*BOFF)             // 36864
#define SMEM_DYN (3*STAGE_B)          // 110592 (x2 CTAs = 221184 <= 228KB)

template<int EPI>
__global__ __launch_bounds__(128, 2)
void k_mma_gemm(const __half* __restrict__ A, const __half* __restrict__ B,
                const float* __restrict__ bias,
                __half* __restrict__ outZ, __half* __restrict__ outV,
                int K, int NK, int ldo)
{
    extern __shared__ char sm[];
    const uint32_t sbase = smem_to_u32(sm);
    const int tid  = threadIdx.x;
    const int wid  = tid >> 5, lane = tid & 31;
    const int wm   = wid >> 1, wn = wid & 1;            // warp grid 2x2
    const int gg   = lane >> 2, tig = lane & 3;
    const int nBase = blockIdx.x * 128;
    const int mBase = blockIdx.y * 128;

    // loader: 1024 16B chunks per array; 8 per thread per array.
    const int cc   = tid & 7;            // 16B segment within 128B row
    const int lrow = tid >> 3;           // 0..15 (+16 x8)

    // ldmatrix thread-address components (64x64 warp tile)
    const int a_row  = wm * 64 + ((lane >> 3) & 1) * 8 + (lane & 7);  // + mi*16
    const int a_col  = (lane >> 4) * 8;                               // + k0
    const int b_row  = wn * 64 + (lane >> 4) * 8 + (lane & 7);        // + nb*16
    const int b_col  = ((lane >> 3) & 1) * 8;                         // + k0

    float acc[4][8][4] = {};

    auto load_stage = [&](int st, int kt) {
        const int koff = kt * 64 + cc * 8;
        const uint32_t db = sbase + st * STAGE_B + cc * 16;
#pragma unroll
        for (int i = 0; i < 8; ++i) {
            const int row = lrow + i * 16;
            ldgsts16(db + row * ROW_T,        A + (size_t)(mBase + row) * K + koff);
            ldgsts16(db + BOFF + row * ROW_T, B + (size_t)(nBase + row) * K + koff);
        }
    };

    load_stage(0, 0); CP_COMMIT();
    load_stage(1, 1); CP_COMMIT();

    for (int kt = 0; kt < NK; ++kt) {
        const int st = kt % 3;
        CP_WAIT1();                       // chunk kt resident
        __syncthreads();

        // prefetch FIRST so cp.async overlaps the MMA block below
        if (kt + 2 < NK) load_stage((kt + 2) % 3, kt + 2);
        CP_COMMIT();                      // uniform group count per iteration

        const uint32_t stb = sbase + st * STAGE_B;
#pragma unroll
        for (int ks = 0; ks < 4; ++ks) {
            const int k0 = ks * 16;
            uint32_t bh[4][4];
#pragma unroll
            for (int nb = 0; nb < 4; ++nb) {
                const uint32_t bd = stb + BOFF
                    + (uint32_t)(b_row + nb * 16) * ROW_T + (k0 + b_col) * 2;
                ldmatrix_x4(bh[nb], bd);
            }
#pragma unroll
            for (int mi = 0; mi < 4; ++mi) {
                uint32_t ah[4];
                const uint32_t ad = stb
                    + (uint32_t)(a_row + mi * 16) * ROW_T + (k0 + a_col) * 2;
                ldmatrix_x4(ah, ad);
#pragma unroll
                for (int ni = 0; ni < 8; ++ni)
                    mma_16816(acc[mi][ni], ah, &bh[ni >> 1][(ni & 1) * 2]);
            }
        }
    }

    // epilogue (register accumulators -> gmem, fp16)
#pragma unroll
    for (int mi = 0; mi < 4; ++mi) {
#pragma unroll
        for (int ni = 0; ni < 8; ++ni) {
            const int row = mBase + wm * 64 + mi * 16 + gg;
            const int col = nBase + wn * 64 + ni * 8 + tig * 2;
            if (EPI == 0) {
                const size_t o0 = (size_t)row * ldo + col;
                const size_t o1 = (size_t)(row + 8) * ldo + col;
                *(__half2*)(outZ + o0) =
                    __halves2half2(__float2half_rn(acc[mi][ni][0]),
                                   __float2half_rn(acc[mi][ni][1]));
                *(__half2*)(outZ + o1) =
                    __halves2half2(__float2half_rn(acc[mi][ni][2]),
                                   __float2half_rn(acc[mi][ni][3]));
            } else {
                const float b0 = bias[col], b1 = bias[col + 1];
                float t0 = tanhf(acc[mi][ni][0] + b0);
                float t1 = tanhf(acc[mi][ni][1] + b1);
                float t2 = tanhf(acc[mi][ni][2] + b0);
                float t3 = tanhf(acc[mi][ni][3] + b1);
                const size_t o0 = (size_t)row * HID_ + col;
                const size_t o1 = (size_t)(row + 8) * HID_ + col;
                *(__half2*)(outV + o0) =
                    __halves2half2(__float2half_rn(t0), __float2half_rn(t1));
                *(__half2*)(outV + o1) =
                    __halves2half2(__float2half_rn(t2), __float2half_rn(t3));
            }
        }
    }
}

// ---------------------------------------------------------------------------
// u = mean over T of v_q
// ---------------------------------------------------------------------------
__global__ void k_mean_vq(const float* __restrict__ vq, float* __restrict__ u) {
    int b = blockIdx.x;
    int h = threadIdx.x;
    const float* p = vq + (size_t)b * T_ * HID_ + h;
    float s = 0.f;
#pragma unroll
    for (int t = 0; t < T_; ++t) s += p[(size_t)t * HID_];
    u[b * HID_ + h] = s * (1.0f / T_);
}

// ---------------------------------------------------------------------------
// fp32 -> fp16 conversions
// ---------------------------------------------------------------------------
__global__ void k_half(const float* __restrict__ x, __half* __restrict__ h, int n) {
    int i = blockIdx.x * 256 + threadIdx.x;
    if (i < n) h[i] = __float2half_rn(x[i]);
}
__global__ void k_half2src(const float* __restrict__ x0, const float* __restrict__ x1,
                           __half* __restrict__ h, int half_n) {
    int i = blockIdx.x * 256 + threadIdx.x;
    if (i < 2 * half_n)
        h[i] = __float2half_rn((i < half_n) ? x0[i] : x1[i - half_n]);
}

// ---------------------------------------------------------------------------
// v_i [B,C,S] -> A1 [B*S, C] fp16 (transpose), 32x32 smem tiles
// ---------------------------------------------------------------------------
__global__ void k_conv_vi(const float* __restrict__ vi, __half* __restrict__ h) {
    __shared__ float t[32][33];
    const int b = blockIdx.x, c0 = blockIdx.y * 32, s0 = blockIdx.z * 32;
    const int tx = threadIdx.x, ty = threadIdx.y;
    const float* src = vi + (size_t)b * C_ * S_;
#pragma unroll
    for (int i = 0; i < 4; ++i) {
        int c = c0 + ty + i * 8;
        int s = s0 + tx;
        t[ty + i * 8][tx] = (s < S_) ? src[(size_t)c * S_ + s] : 0.f;
    }
    __syncthreads();
#pragma unroll
    for (int i = 0; i < 4; ++i) {
        int s = s0 + ty + i * 8;
        if (s < S_) {
            int c = c0 + tx;
            h[((size_t)b * S_ + s) * C_ + c] = __float2half_rn(t[tx][ty + i * 8]);
        }
    }
}

// ---------------------------------------------------------------------------
// vqt = u @ w_u^T + b_u   [128,1024] x [1024,1024]^T — 64 blocks, 2 b each
// ---------------------------------------------------------------------------
__global__ __launch_bounds__(256)
void k_vqt(const float* __restrict__ u, const float* __restrict__ wu,
           const float* __restrict__ bu, float* __restrict__ vqt) {
    __shared__ float us[2][HID_];
    const int b0 = blockIdx.x * 2;
    const int tid = threadIdx.x;
    for (int i = tid; i < 2 * HID_; i += 256)
        us[i >> 10][i & 1023] = u[(size_t)b0 * HID_ + i];
    __syncthreads();
    const int h0 = tid * 4;
    float acc[2][4] = {};
    for (int k = 0; k < HID_; k += 4) {
        float4 u0 = *(const float4*)&us[0][k];
        float4 u1 = *(const float4*)&us[1][k];
#pragma unroll
        for (int j = 0; j < 4; ++j) {
            float4 w = *(const float4*)&wu[(size_t)(h0 + j) * HID_ + k];
            acc[0][j] += u0.x * w.x + u0.y * w.y + u0.z * w.z + u0.w * w.w;
            acc[1][j] += u1.x * w.x + u1.y * w.y + u1.z * w.z + u1.w * w.w;
        }
    }
#pragma unroll
    for (int j = 0; j < 4; ++j) {
        float bb = bu[h0 + j];
        vqt[(size_t)b0 * HID_ + h0 + j]       = acc[0][j] + bb;
        vqt[(size_t)(b0 + 1) * HID_ + h0 + j] = acc[1][j] + bb;
    }
}

// ---------------------------------------------------------------------------
// Fused attention tail (single pass; tanh bounds exp, no max needed):
// u_out = u_in + (sum_s e*vi) / (sum_s e), e = exp(tanh(z + vqt))
// Z fp16 with leading dim 2*HID_ (z0|z1); caller passes hop offset.
// ---------------------------------------------------------------------------
__global__ __launch_bounds__(256)
void k_attn(const __half* __restrict__ Z, const __half* __restrict__ vh,
            const float* __restrict__ vqt, const float* __restrict__ uin,
            float* __restrict__ uout) {
    const int b = blockIdx.x;
    const int t = threadIdx.x;
    float vq[4], ae[4], av[4];
#pragma unroll
    for (int j = 0; j < 4; ++j) {
        vq[j] = vqt[b * HID_ + t + j * 256];
        ae[j] = 0.f; av[j] = 0.f;
    }
    const __half* zp  = Z  + (size_t)b * S_ * (2 * HID_) + t;
    const __half* vph = vh + (size_t)b * S_ * HID_ + t;
    for (int s = 0; s < S_; ++s) {
#pragma unroll
        for (int j = 0; j < 4; ++j) {
            float z = __half2float(zp[(size_t)s * (2 * HID_) + j * 256]);
            float v = __half2float(vph[(size_t)s * HID_ + j * 256]);
            float e = __expf(tanhf(z + vq[j]));
            ae[j] += e;
            av[j] += e * v;
        }
    }
#pragma unroll
    for (int j = 0; j < 4; ++j) {
        int idx = b * HID_ + t + j * 256;
        uout[idx] = uin[idx] + av[j] / ae[j];
    }
}

// ---------------------------------------------------------------------------
// Launch.  Inputs: 0 v_i, 1 v_q, 2 l1_w, 3 l1_b, 4 w_vi0, 5 w_u0, 6 b_u0,
//                  7 w_vi1, 8 w_u1, 9 b_u1
// ---------------------------------------------------------------------------
extern "C" void kernel_launch(void* const* d_in, const int* in_sizes, int n_in,
                              void* d_out, int out_size) {
    const float* v_i  = (const float*)d_in[0];
    const float* v_q  = (const float*)d_in[1];
    const float* l1_w = (const float*)d_in[2];
    const float* l1_b = (const float*)d_in[3];
    const float* w_vi0= (const float*)d_in[4];
    const float* w_u0 = (const float*)d_in[5];
    const float* b_u0 = (const float*)d_in[6];
    const float* w_vi1= (const float*)d_in[7];
    const float* w_u1 = (const float*)d_in[8];
    const float* b_u1 = (const float*)d_in[9];
    float* out = (float*)d_out;

    __half *p_a1, *p_vi, *p_z, *p_l1w, *p_wc;
    float *p_u0, *p_u1, *p_vqt;
    cudaGetSymbolAddress((void**)&p_a1,  g_a1);
    cudaGetSymbolAddress((void**)&p_vi,  g_vi);
    cudaGetSymbolAddress((void**)&p_z,   g_z);
    cudaGetSymbolAddress((void**)&p_l1w, g_l1w);
    cudaGetSymbolAddress((void**)&p_wc,  g_wc);
    cudaGetSymbolAddress((void**)&p_u0,  g_u0);
    cudaGetSymbolAddress((void**)&p_u1,  g_u1);
    cudaGetSymbolAddress((void**)&p_vqt, g_vqt);

    cudaFuncSetAttribute(k_mma_gemm<0>, cudaFuncAttributeMaxDynamicSharedMemorySize, SMEM_DYN);
    cudaFuncSetAttribute(k_mma_gemm<1>, cudaFuncAttributeMaxDynamicSharedMemorySize, SMEM_DYN);

    // 1: v_i transpose -> fp16
    {
        dim3 g(B_, C_ / 32, (S_ + 31) / 32);
        k_conv_vi<<<g, dim3(32, 8)>>>(v_i, p_a1);
    }
    // 2: l1_w -> fp16
    k_half<<<(HID_ * C_ + 255) / 256, 256>>>(l1_w, p_l1w, HID_ * C_);
    // 3: GEMM1 vi = tanh(A1 @ l1_w^T + l1_b) -> fp16
    {
        dim3 g(HID_ / 128, M_ / 128);
        k_mma_gemm<1><<<g, 128, SMEM_DYN>>>(p_a1, p_l1w, l1_b, nullptr, p_vi,
                                            C_, C_ / 64, HID_);
    }
    // 4: w0|w1 concat -> fp16
    k_half2src<<<(2 * HID_ * HID_ + 255) / 256, 256>>>(w_vi0, w_vi1, p_wc, HID_ * HID_);
    // 5: u0 = mean_t v_q
    k_mean_vq<<<B_, HID_>>>(v_q, p_u0);
    // 6: merged hop GEMM  z0|z1 = vi @ [w0|w1]^T  [M,2048] fp16
    {
        dim3 g(2 * HID_ / 128, M_ / 128);   // 16 x 196
        k_mma_gemm<0><<<g, 128, SMEM_DYN>>>(p_vi, p_wc, nullptr, p_z, nullptr,
                                            HID_, HID_ / 64, 2 * HID_);
    }
    // 7-10: attention chain
    k_vqt<<<B_ / 2, 256>>>(p_u0, w_u0, b_u0, p_vqt);
    k_attn<<<B_, 256>>>(p_z,        p_vi, p_vqt, p_u0, p_u1);
    k_vqt<<<B_ / 2, 256>>>(p_u1, w_u1, b_u1, p_vqt);
    k_attn<<<B_, 256>>>(p_z + HID_, p_vi, p_vqt, p_u1, out);
}